// round 1
// baseline (speedup 1.0000x reference)
#include <cuda_runtime.h>
#include <math.h>

#define BATCH  4
#define SEQ    1024
#define DMODEL 1024
#define NH     16
#define DK     64

// Scratch (device globals: allocation-free per harness rules)
__device__ float g_Q[BATCH * NH * SEQ * DK];                 // [b,h,s,dk] 16 MB
__device__ float g_K[BATCH * NH * SEQ * DK];
__device__ float g_V[BATCH * NH * SEQ * DK];
__device__ float g_bias[BATCH * NH * SEQ * SEQ];             // [b,h,q,k] 268 MB
__device__ float g_ctx[BATCH * SEQ * DMODEL];                // [b,s,d]   16 MB

// ---------------------------------------------------------------------------
// GEMM: C[M,N] = A[M,K] @ W[K,N] + bias[N]
// M=4096, N=K=1024. 128x128 block tile, BK=8, 256 threads, 8x8 micro-tile.
// mode 0/1/2: write Q/K/V in [b,h,s,dk] layout (A = x param)
// mode 3:     A = g_ctx, write plain [m,n] to C param (final projection)
// ---------------------------------------------------------------------------
__global__ __launch_bounds__(256, 2)
void gemm_bias_kernel(const float* __restrict__ A, const float* __restrict__ W,
                      const float* __restrict__ bias, float* __restrict__ C, int mode)
{
    const int N = 1024, K = 1024;
    __shared__ float As[8][128];
    __shared__ float Ws[8][128];

    const float* Asrc = (mode == 3) ? g_ctx : A;
    float* dst = (mode == 0) ? g_Q : (mode == 1) ? g_K : (mode == 2) ? g_V : C;

    const int tid = threadIdx.x;
    const int bm = blockIdx.y * 128;
    const int bn = blockIdx.x * 128;
    const int arow = tid >> 1;          // 0..127
    const int acol = (tid & 1) * 4;     // 0 or 4
    const int wrow = tid >> 5;          // 0..7
    const int wcol = (tid & 31) * 4;    // 0..124
    const int tx = tid & 15;
    const int ty = tid >> 4;

    const float* Ap = Asrc + (size_t)(bm + arow) * K + acol;
    const float* Wp = W + (size_t)wrow * N + bn + wcol;

    float acc[8][8];
    #pragma unroll
    for (int i = 0; i < 8; i++)
        #pragma unroll
        for (int j = 0; j < 8; j++) acc[i][j] = 0.f;

    for (int k0 = 0; k0 < K; k0 += 8) {
        float4 av = *(const float4*)(Ap + k0);
        float4 wv = *(const float4*)(Wp + (size_t)k0 * N);
        __syncthreads();
        As[acol + 0][arow] = av.x;
        As[acol + 1][arow] = av.y;
        As[acol + 2][arow] = av.z;
        As[acol + 3][arow] = av.w;
        *(float4*)&Ws[wrow][wcol] = wv;
        __syncthreads();
        #pragma unroll
        for (int kk = 0; kk < 8; kk++) {
            float a[8], w[8];
            *(float4*)&a[0] = *(const float4*)&As[kk][ty * 4];
            *(float4*)&a[4] = *(const float4*)&As[kk][64 + ty * 4];
            *(float4*)&w[0] = *(const float4*)&Ws[kk][tx * 4];
            *(float4*)&w[4] = *(const float4*)&Ws[kk][64 + tx * 4];
            #pragma unroll
            for (int i = 0; i < 8; i++)
                #pragma unroll
                for (int j = 0; j < 8; j++)
                    acc[i][j] += a[i] * w[j];
        }
    }

    const bool qkv = (mode < 3);
    #pragma unroll
    for (int i = 0; i < 8; i++) {
        int m = bm + ((i < 4) ? (ty * 4 + i) : (64 + ty * 4 + (i - 4)));
        #pragma unroll
        for (int j = 0; j < 8; j++) {
            int n = bn + ((j < 4) ? (tx * 4 + j) : (64 + tx * 4 + (j - 4)));
            float v = acc[i][j] + bias[n];
            if (qkv) {
                int b = m >> 10, s = m & 1023;
                int h = n >> 6,  d = n & 63;
                dst[(size_t)((b * NH + h) * SEQ + s) * DK + d] = v;
            } else {
                dst[(size_t)m * N + n] = v;
            }
        }
    }
}

// ---------------------------------------------------------------------------
// Geometry bias: g_bias[b,h,q,k] = sum_g geom[b,q,k,g] * Wg[g,h] + bg[h]
// One thread per (b,q,k).
// ---------------------------------------------------------------------------
__global__ __launch_bounds__(256)
void geom_bias_kernel(const float* __restrict__ geom, const float* __restrict__ Wg,
                      const float* __restrict__ bg)
{
    __shared__ float wgs[7][16];
    __shared__ float bgs[16];
    int tid = threadIdx.x;
    if (tid < 112) wgs[tid / 16][tid % 16] = Wg[tid];
    if (tid < 16)  bgs[tid] = bg[tid];
    __syncthreads();

    size_t idx = (size_t)blockIdx.x * 256 + tid;   // 0 .. B*S*S-1
    const float* gp = geom + idx * 7;
    float g[7];
    #pragma unroll
    for (int i = 0; i < 7; i++) g[i] = gp[i];

    int k = (int)(idx & 1023);
    int bq = (int)(idx >> 10);
    int q = bq & 1023;
    int b = bq >> 10;
    size_t base = ((size_t)(b * NH) * SEQ + q) * SEQ + k;

    #pragma unroll
    for (int h = 0; h < NH; h++) {
        float v = bgs[h];
        #pragma unroll
        for (int i = 0; i < 7; i++) v += g[i] * wgs[i][h];
        g_bias[base + (size_t)h * SEQ * SEQ] = v;
    }
}

// ---------------------------------------------------------------------------
// Flash-style attention with fused geometric bias + key-padding mask.
// Block = (b, h, q-tile of 64). 256 threads, 4x4 micro-tiles.
// Dynamic smem (~66 KB): Qt[d][q], Kt[d][k], Vs[k][d], Pt[k][q] (+pad),
// running max/sum/rescale, mask tile.
// ---------------------------------------------------------------------------
#define ATTN_SMEM_BYTES ((64*64*3 + 64*68 + 64*3) * 4 + 64 * 4)

__global__ __launch_bounds__(256)
void attn_kernel(const int* __restrict__ mask)
{
    extern __shared__ float sm[];
    float* Qt  = sm;                  // [64][64] d-major
    float* Kt  = Qt + 64 * 64;        // [64][64] d-major
    float* Vs  = Kt + 64 * 64;        // [64][64] k-major
    float* Pt  = Vs + 64 * 64;        // [64][68] k-major (pad 68 for align+banks)
    float* m_s = Pt + 64 * 68;
    float* l_s = m_s + 64;
    float* sc_s = l_s + 64;
    int*   mk_s = (int*)(sc_s + 64);

    const int qb = blockIdx.x * 64;
    const int h  = blockIdx.y;
    const int b  = blockIdx.z;
    const float* Qp = g_Q + (size_t)((b * NH + h) * SEQ) * DK;
    const float* Kp = g_K + (size_t)((b * NH + h) * SEQ) * DK;
    const float* Vp = g_V + (size_t)((b * NH + h) * SEQ) * DK;
    const float* Bp = g_bias + (size_t)(b * NH + h) * SEQ * SEQ;
    const int*   Mp = mask + b * SEQ;

    const int tid  = threadIdx.x;
    const int tx   = tid & 15, ty = tid >> 4;
    const int lane = tid & 31, warp = tid >> 5;

    // Load Q tile transposed: Qt[d][q]
    {
        int q  = tid >> 2;
        int d0 = (tid & 3) * 16;
        #pragma unroll
        for (int c = 0; c < 16; c += 4) {
            float4 v = *(const float4*)(Qp + (size_t)(qb + q) * DK + d0 + c);
            Qt[(d0 + c + 0) * 64 + q] = v.x;
            Qt[(d0 + c + 1) * 64 + q] = v.y;
            Qt[(d0 + c + 2) * 64 + q] = v.z;
            Qt[(d0 + c + 3) * 64 + q] = v.w;
        }
    }
    if (tid < 64) { m_s[tid] = -1e30f; l_s[tid] = 0.f; }

    float acc[4][4];
    #pragma unroll
    for (int i = 0; i < 4; i++)
        #pragma unroll
        for (int j = 0; j < 4; j++) acc[i][j] = 0.f;

    for (int kt = 0; kt < 16; kt++) {
        const int kb = kt * 64;
        __syncthreads();   // protect smem reuse from previous iteration's reads
        {
            int r  = tid >> 2;
            int c0 = (tid & 3) * 16;
            #pragma unroll
            for (int c = 0; c < 16; c += 4) {
                float4 kv = *(const float4*)(Kp + (size_t)(kb + r) * DK + c0 + c);
                Kt[(c0 + c + 0) * 64 + r] = kv.x;
                Kt[(c0 + c + 1) * 64 + r] = kv.y;
                Kt[(c0 + c + 2) * 64 + r] = kv.z;
                Kt[(c0 + c + 3) * 64 + r] = kv.w;
                float4 vv = *(const float4*)(Vp + (size_t)(kb + r) * DK + c0 + c);
                *(float4*)&Vs[r * 64 + c0 + c] = vv;
            }
        }
        if (tid < 64) mk_s[tid] = Mp[kb + tid];
        __syncthreads();

        // S = Q K^T (4x4 micro-tile per thread)
        float s[4][4];
        #pragma unroll
        for (int i = 0; i < 4; i++)
            #pragma unroll
            for (int j = 0; j < 4; j++) s[i][j] = 0.f;
        #pragma unroll
        for (int d = 0; d < 64; d++) {
            float a[4], kf[4];
            *(float4*)a  = *(const float4*)&Qt[d * 64 + ty * 4];
            *(float4*)kf = *(const float4*)&Kt[d * 64 + tx * 4];
            #pragma unroll
            for (int i = 0; i < 4; i++)
                #pragma unroll
                for (int j = 0; j < 4; j++)
                    s[i][j] += a[i] * kf[j];
        }

        // scale + bias + mask -> Pt[k][q]
        #pragma unroll
        for (int i = 0; i < 4; i++) {
            int q = ty * 4 + i;
            float4 bv = *(const float4*)(Bp + (size_t)(qb + q) * SEQ + kb + tx * 4);
            float bb[4] = {bv.x, bv.y, bv.z, bv.w};
            #pragma unroll
            for (int j = 0; j < 4; j++) {
                int k = tx * 4 + j;
                float v = (mk_s[k] == 0) ? -10000.f : (s[i][j] * 0.125f + bb[j]);
                Pt[k * 68 + q] = v;
            }
        }
        __syncthreads();

        // Online softmax: warp w handles rows [8w, 8w+8)
        #pragma unroll
        for (int r = 0; r < 8; r++) {
            int q = warp * 8 + r;
            float v1 = Pt[lane * 68 + q];
            float v2 = Pt[(lane + 32) * 68 + q];
            float mx = fmaxf(v1, v2);
            #pragma unroll
            for (int o = 16; o > 0; o >>= 1)
                mx = fmaxf(mx, __shfl_xor_sync(0xffffffffu, mx, o));
            float m_old = m_s[q];
            float m_new = fmaxf(m_old, mx);
            float e1 = __expf(v1 - m_new);
            float e2 = __expf(v2 - m_new);
            Pt[lane * 68 + q] = e1;
            Pt[(lane + 32) * 68 + q] = e2;
            float sum = e1 + e2;
            #pragma unroll
            for (int o = 16; o > 0; o >>= 1)
                sum += __shfl_xor_sync(0xffffffffu, sum, o);
            if (lane == 0) {
                float scl = __expf(m_old - m_new);
                l_s[q] = l_s[q] * scl + sum;
                m_s[q] = m_new;
                sc_s[q] = scl;
            }
        }
        __syncthreads();

        // Rescale accumulators, then O += P V
        float scl[4];
        #pragma unroll
        for (int i = 0; i < 4; i++) scl[i] = sc_s[ty * 4 + i];
        #pragma unroll
        for (int i = 0; i < 4; i++)
            #pragma unroll
            for (int j = 0; j < 4; j++) acc[i][j] *= scl[i];

        #pragma unroll
        for (int k = 0; k < 64; k++) {
            float p[4], v[4];
            *(float4*)p = *(const float4*)&Pt[k * 68 + ty * 4];
            *(float4*)v = *(const float4*)&Vs[k * 64 + tx * 4];
            #pragma unroll
            for (int i = 0; i < 4; i++)
                #pragma unroll
                for (int j = 0; j < 4; j++)
                    acc[i][j] += p[i] * v[j];
        }
    }

    // Normalize and write ctx[b, s, h*64 + d]
    #pragma unroll
    for (int i = 0; i < 4; i++) {
        int q = ty * 4 + i;
        float inv = 1.f / l_s[q];
        float4 o;
        o.x = acc[i][0] * inv;
        o.y = acc[i][1] * inv;
        o.z = acc[i][2] * inv;
        o.w = acc[i][3] * inv;
        *(float4*)(g_ctx + (size_t)(b * SEQ + qb + q) * DMODEL + h * 64 + tx * 4) = o;
    }
}

// ---------------------------------------------------------------------------
extern "C" void kernel_launch(void* const* d_in, const int* in_sizes, int n_in,
                              void* d_out, int out_size)
{
    const float* x    = (const float*)d_in[0];
    const float* geom = (const float*)d_in[1];
    const int*   mask = (const int*)d_in[2];
    const float* Wq = (const float*)d_in[3];
    const float* bq = (const float*)d_in[4];
    const float* Wk = (const float*)d_in[5];
    const float* bk = (const float*)d_in[6];
    const float* Wv = (const float*)d_in[7];
    const float* bv = (const float*)d_in[8];
    const float* Wo = (const float*)d_in[9];
    const float* bo = (const float*)d_in[10];
    const float* Wg = (const float*)d_in[11];
    const float* bg = (const float*)d_in[12];
    float* out = (float*)d_out;

    dim3 gg(1024 / 128, 4096 / 128);   // (8, 32)

    gemm_bias_kernel<<<gg, 256>>>(x, Wq, bq, nullptr, 0);   // -> g_Q
    gemm_bias_kernel<<<gg, 256>>>(x, Wk, bk, nullptr, 1);   // -> g_K
    gemm_bias_kernel<<<gg, 256>>>(x, Wv, bv, nullptr, 2);   // -> g_V

    geom_bias_kernel<<<(BATCH * SEQ * SEQ) / 256, 256>>>(geom, Wg, bg);

    cudaFuncSetAttribute(attn_kernel,
                         cudaFuncAttributeMaxDynamicSharedMemorySize,
                         ATTN_SMEM_BYTES);
    attn_kernel<<<dim3(SEQ / 64, NH, BATCH), 256, ATTN_SMEM_BYTES>>>(mask);

    gemm_bias_kernel<<<gg, 256>>>(nullptr, Wo, bo, out, 3); // g_ctx @ Wo -> out
}

// round 3
// speedup vs baseline: 1.9753x; 1.9753x over previous
#include <cuda_runtime.h>
#include <math.h>
#include <cstdint>

#define BATCH  4
#define SEQ    1024
#define DMODEL 1024
#define NH     16
#define DK     64

// ---------------- scratch (device globals: allocation-free) ----------------
__device__ float g_Q[BATCH * NH * SEQ * DK];
__device__ float g_K[BATCH * NH * SEQ * DK];
__device__ float g_V[BATCH * NH * SEQ * DK];
__device__ float g_bias[BATCH * NH * SEQ * SEQ];   // 268 MB
__device__ float g_ctx[BATCH * SEQ * DMODEL];

// ---------------- mma.sync tf32 helpers (family-portable PTX) ----------------
__device__ __forceinline__ float to_tf32(float x) {
    uint32_t u;
    asm("cvt.rna.tf32.f32 %0, %1;" : "=r"(u) : "f"(x));
    return __uint_as_float(u);
}
__device__ __forceinline__ void mma_tf32(float c[4], const uint32_t a[4], const uint32_t b[2]) {
    asm volatile("mma.sync.aligned.m16n8k8.row.col.f32.tf32.tf32.f32 "
                 "{%0,%1,%2,%3}, {%4,%5,%6,%7}, {%8,%9}, {%0,%1,%2,%3};"
                 : "+f"(c[0]), "+f"(c[1]), "+f"(c[2]), "+f"(c[3])
                 : "r"(a[0]), "r"(a[1]), "r"(a[2]), "r"(a[3]), "r"(b[0]), "r"(b[1]));
}

// ---------------------------------------------------------------------------
// Tensor GEMM via mma.sync tf32: C[M,N] = A[M,1024] @ W[1024,N] + bias
// CTA 128x128, 8 warps (4x2), warp tile 32x64, k-slab 32 double-buffered.
// mode 0: QKV fused (blockIdx.x: mat = x>>3, ntile = x&7) -> [b,h,s,dk] layout
// mode 1: out projection: A = g_ctx, write [m][n] to Cout
// ---------------------------------------------------------------------------
#define AP 36                    // A smem row stride (128 x 36)
#define BP 136                   // B smem row stride (32 x 136)
#define GBUF (128 * AP + 32 * BP)            // floats per buffer = 8960
#define GSMEM_BYTES (2 * GBUF * 4)           // 71680 B

__global__ __launch_bounds__(256)
void gemm_mma(const float* __restrict__ A,
              const float* __restrict__ W0, const float* __restrict__ W1,
              const float* __restrict__ W2,
              const float* __restrict__ bias0, const float* __restrict__ bias1,
              const float* __restrict__ bias2,
              float* __restrict__ Cout, int mode)
{
    extern __shared__ float smg[];
    const int tid = threadIdx.x, lane = tid & 31;
    const int wid = tid >> 5;
    const int wm = wid & 3, wn = wid >> 2;
    const int r = lane >> 2, c = lane & 3;

    int mat, bn;
    const float* W;
    const float* bias;
    if (mode == 0) {
        mat = blockIdx.x >> 3;
        bn = (blockIdx.x & 7) * 128;
        W = (mat == 0) ? W0 : (mat == 1) ? W1 : W2;
        bias = (mat == 0) ? bias0 : (mat == 1) ? bias1 : bias2;
    } else {
        mat = 3;
        bn = blockIdx.x * 128;
        W = W0;
        bias = bias0;
    }
    const int bm = blockIdx.y * 128;
    const float* Asrc = (mode == 0) ? A : g_ctx;

    // global load mapping
    const int arow = tid >> 1;            // 0..127
    const int acb  = (tid & 1) * 16;      // 0 / 16
    const int brow = tid >> 3;            // 0..31 (k)
    const int bcb  = (tid & 7) * 16;      // 0..112 (n)
    const float* Apg = Asrc + (size_t)(bm + arow) * 1024 + acb;
    const float* Bpg = W + (size_t)brow * 1024 + bn + bcb;

    float acc[2][8][4];
    #pragma unroll
    for (int im = 0; im < 2; im++)
        #pragma unroll
        for (int in_ = 0; in_ < 8; in_++)
            #pragma unroll
            for (int j = 0; j < 4; j++) acc[im][in_][j] = 0.f;

    float4 ar[4], br[4];
    #pragma unroll
    for (int j = 0; j < 4; j++) {
        ar[j] = *(const float4*)(Apg + j * 4);
        br[j] = *(const float4*)(Bpg + (size_t)0 + j * 4);
    }
    // store slab 0 -> buf 0 (converted to tf32)
    {
        float* Ab = smg;
        float* Bb = smg + 128 * AP;
        #pragma unroll
        for (int j = 0; j < 4; j++) {
            float4 t = { to_tf32(ar[j].x), to_tf32(ar[j].y), to_tf32(ar[j].z), to_tf32(ar[j].w) };
            *(float4*)&Ab[arow * AP + acb + j * 4] = t;
            float4 u = { to_tf32(br[j].x), to_tf32(br[j].y), to_tf32(br[j].z), to_tf32(br[j].w) };
            *(float4*)&Bb[brow * BP + bcb + j * 4] = u;
        }
    }
    __syncthreads();

    for (int s = 0; s < 32; s++) {
        if (s + 1 < 32) {
            const int k0 = (s + 1) * 32;
            #pragma unroll
            for (int j = 0; j < 4; j++) {
                ar[j] = *(const float4*)(Apg + k0 + j * 4);
                br[j] = *(const float4*)(Bpg + (size_t)k0 * 1024 + j * 4);
            }
        }
        const float* Ab = smg + (s & 1) * GBUF;
        const float* Bb = Ab + 128 * AP;
        #pragma unroll
        for (int ks = 0; ks < 4; ks++) {
            uint32_t af[2][4];
            #pragma unroll
            for (int im = 0; im < 2; im++) {
                const int m0 = wm * 32 + im * 16;
                af[im][0] = __float_as_uint(Ab[(m0 + r) * AP + ks * 8 + c]);
                af[im][1] = __float_as_uint(Ab[(m0 + r + 8) * AP + ks * 8 + c]);
                af[im][2] = __float_as_uint(Ab[(m0 + r) * AP + ks * 8 + c + 4]);
                af[im][3] = __float_as_uint(Ab[(m0 + r + 8) * AP + ks * 8 + c + 4]);
            }
            #pragma unroll
            for (int in_ = 0; in_ < 8; in_++) {
                const int n0 = wn * 64 + in_ * 8;
                uint32_t bf[2];
                bf[0] = __float_as_uint(Bb[(ks * 8 + c) * BP + n0 + r]);
                bf[1] = __float_as_uint(Bb[(ks * 8 + c + 4) * BP + n0 + r]);
                mma_tf32(acc[0][in_], af[0], bf);
                mma_tf32(acc[1][in_], af[1], bf);
            }
        }
        if (s + 1 < 32) {
            float* Ab2 = smg + ((s + 1) & 1) * GBUF;
            float* Bb2 = Ab2 + 128 * AP;
            #pragma unroll
            for (int j = 0; j < 4; j++) {
                float4 t = { to_tf32(ar[j].x), to_tf32(ar[j].y), to_tf32(ar[j].z), to_tf32(ar[j].w) };
                *(float4*)&Ab2[arow * AP + acb + j * 4] = t;
                float4 u = { to_tf32(br[j].x), to_tf32(br[j].y), to_tf32(br[j].z), to_tf32(br[j].w) };
                *(float4*)&Bb2[brow * BP + bcb + j * 4] = u;
            }
        }
        __syncthreads();
    }

    // epilogue: bias add + store
    #pragma unroll
    for (int im = 0; im < 2; im++) {
        #pragma unroll
        for (int in_ = 0; in_ < 8; in_++) {
            const int m = bm + wm * 32 + im * 16 + r;
            const int n = bn + wn * 64 + in_ * 8 + 2 * c;
            float2 bz = *(const float2*)&bias[n];
            float2 v0 = { acc[im][in_][0] + bz.x, acc[im][in_][1] + bz.y };
            float2 v1 = { acc[im][in_][2] + bz.x, acc[im][in_][3] + bz.y };
            if (mode == 0) {
                const int bb = m >> 10, ss = m & 1023;
                const int hh = n >> 6, dd = n & 63;
                float* dst = ((mat == 0) ? g_Q : (mat == 1) ? g_K : g_V)
                           + ((size_t)((bb * NH + hh) * SEQ + ss)) * DK + dd;
                *(float2*)dst = v0;
                *(float2*)(dst + 8 * DK) = v1;
            } else {
                float* dst = Cout + (size_t)m * 1024 + n;
                *(float2*)dst = v0;
                *(float2*)(dst + 8 * 1024) = v1;
            }
        }
    }
}

// ---------------------------------------------------------------------------
// Geometry bias: g_bias[b,h,q,k] = geom[b,q,k,:] @ Wg + bg
// ---------------------------------------------------------------------------
__global__ __launch_bounds__(256)
void geom_bias_kernel(const float* __restrict__ geom, const float* __restrict__ Wg,
                      const float* __restrict__ bg)
{
    __shared__ float wgs[7][16];
    __shared__ float bgs[16];
    int tid = threadIdx.x;
    if (tid < 112) wgs[tid / 16][tid % 16] = Wg[tid];
    if (tid < 16)  bgs[tid] = bg[tid];
    __syncthreads();

    size_t idx = (size_t)blockIdx.x * 256 + tid;
    const float* gp = geom + idx * 7;
    float g[7];
    #pragma unroll
    for (int i = 0; i < 7; i++) g[i] = gp[i];

    int k = (int)(idx & 1023);
    int bq = (int)(idx >> 10);
    int q = bq & 1023;
    int b = bq >> 10;
    size_t base = ((size_t)(b * NH) * SEQ + q) * SEQ + k;

    #pragma unroll
    for (int h = 0; h < NH; h++) {
        float v = bgs[h];
        #pragma unroll
        for (int i = 0; i < 7; i++) v += g[i] * wgs[i][h];
        g_bias[base + (size_t)h * SEQ * SEQ] = v;
    }
}

// ---------------------------------------------------------------------------
// Flash attention via mma.sync tf32. 128 threads (4 warps x 16 q-rows).
// Register online softmax on C-fragments; P roundtrip through smem (warp-local).
// ---------------------------------------------------------------------------
#define AQ 68   // Qs/Ks/Ps row stride
#define AV 72   // Vs row stride
#define ASMEM_BYTES ((64 * AQ * 3 + 64 * AV) * 4 + 64 * 4)

__global__ __launch_bounds__(128, 2)
void attn_mma(const int* __restrict__ mask)
{
    extern __shared__ float smf[];
    float* Qs = smf;                 // [64][AQ]
    float* Ks = Qs + 64 * AQ;        // [64][AQ]
    float* Ps = Ks + 64 * AQ;        // [64][AQ]
    float* Vs = Ps + 64 * AQ;        // [64][AV]
    int*   mk_s = (int*)(Vs + 64 * AV);

    const int qb = blockIdx.x * 64;
    const int h  = blockIdx.y;
    const int b  = blockIdx.z;
    const float* Qp = g_Q + (size_t)((b * NH + h) * SEQ) * DK;
    const float* Kp = g_K + (size_t)((b * NH + h) * SEQ) * DK;
    const float* Vp = g_V + (size_t)((b * NH + h) * SEQ) * DK;
    const float* Bbp = g_bias + (size_t)(b * NH + h) * SEQ * SEQ;
    const int*   Mp = mask + b * SEQ;

    const int tid = threadIdx.x;
    const int lane = tid & 31, wid = tid >> 5;
    const int r = lane >> 2, c = lane & 3;
    const int q0 = wid * 16;

    // load Q tile (tf32-converted), [q][d]
    {
        const int row = tid >> 1;
        const int cb  = (tid & 1) * 32;
        #pragma unroll
        for (int j = 0; j < 8; j++) {
            float4 v = *(const float4*)(Qp + (size_t)(qb + row) * DK + cb + j * 4);
            float4 t = { to_tf32(v.x), to_tf32(v.y), to_tf32(v.z), to_tf32(v.w) };
            *(float4*)&Qs[row * AQ + cb + j * 4] = t;
        }
    }

    float oAcc[8][4];
    #pragma unroll
    for (int dt = 0; dt < 8; dt++)
        #pragma unroll
        for (int j = 0; j < 4; j++) oAcc[dt][j] = 0.f;
    float mA = -1e30f, mB = -1e30f, lA = 0.f, lB = 0.f;

    for (int kt = 0; kt < 16; kt++) {
        const int kb = kt * 64;
        __syncthreads();
        {
            const int row = tid >> 1;
            const int cb  = (tid & 1) * 32;
            #pragma unroll
            for (int j = 0; j < 8; j++) {
                float4 kv = *(const float4*)(Kp + (size_t)(kb + row) * DK + cb + j * 4);
                float4 t = { to_tf32(kv.x), to_tf32(kv.y), to_tf32(kv.z), to_tf32(kv.w) };
                *(float4*)&Ks[row * AQ + cb + j * 4] = t;
                float4 vv = *(const float4*)(Vp + (size_t)(kb + row) * DK + cb + j * 4);
                float4 u = { to_tf32(vv.x), to_tf32(vv.y), to_tf32(vv.z), to_tf32(vv.w) };
                *(float4*)&Vs[row * AV + cb + j * 4] = u;
            }
        }
        if (tid < 64) mk_s[tid] = Mp[kb + tid];
        __syncthreads();

        // S = Q K^T
        float sAcc[8][4];
        #pragma unroll
        for (int nt = 0; nt < 8; nt++)
            #pragma unroll
            for (int j = 0; j < 4; j++) sAcc[nt][j] = 0.f;
        #pragma unroll
        for (int ks = 0; ks < 8; ks++) {
            uint32_t af[4];
            af[0] = __float_as_uint(Qs[(q0 + r) * AQ + ks * 8 + c]);
            af[1] = __float_as_uint(Qs[(q0 + r + 8) * AQ + ks * 8 + c]);
            af[2] = __float_as_uint(Qs[(q0 + r) * AQ + ks * 8 + c + 4]);
            af[3] = __float_as_uint(Qs[(q0 + r + 8) * AQ + ks * 8 + c + 4]);
            #pragma unroll
            for (int nt = 0; nt < 8; nt++) {
                uint32_t bf[2];
                bf[0] = __float_as_uint(Ks[(nt * 8 + r) * AQ + ks * 8 + c]);
                bf[1] = __float_as_uint(Ks[(nt * 8 + r) * AQ + ks * 8 + c + 4]);
                mma_tf32(sAcc[nt], af, bf);
            }
        }

        // scale + bias + mask (in place), track row max
        float mxA = -1e30f, mxB = -1e30f;
        const float* BpA = Bbp + (size_t)(qb + q0 + r) * SEQ + kb;
        const float* BpB = BpA + (size_t)8 * SEQ;
        #pragma unroll
        for (int nt = 0; nt < 8; nt++) {
            const int k2 = nt * 8 + 2 * c;
            float2 bzA = *(const float2*)(BpA + k2);
            float2 bzB = *(const float2*)(BpB + k2);
            const bool m0 = mk_s[k2] != 0;
            const bool m1 = mk_s[k2 + 1] != 0;
            sAcc[nt][0] = m0 ? fmaf(sAcc[nt][0], 0.125f, bzA.x) : -10000.f;
            sAcc[nt][1] = m1 ? fmaf(sAcc[nt][1], 0.125f, bzA.y) : -10000.f;
            sAcc[nt][2] = m0 ? fmaf(sAcc[nt][2], 0.125f, bzB.x) : -10000.f;
            sAcc[nt][3] = m1 ? fmaf(sAcc[nt][3], 0.125f, bzB.y) : -10000.f;
            mxA = fmaxf(mxA, fmaxf(sAcc[nt][0], sAcc[nt][1]));
            mxB = fmaxf(mxB, fmaxf(sAcc[nt][2], sAcc[nt][3]));
        }
        mxA = fmaxf(mxA, __shfl_xor_sync(0xffffffffu, mxA, 1));
        mxA = fmaxf(mxA, __shfl_xor_sync(0xffffffffu, mxA, 2));
        mxB = fmaxf(mxB, __shfl_xor_sync(0xffffffffu, mxB, 1));
        mxB = fmaxf(mxB, __shfl_xor_sync(0xffffffffu, mxB, 2));

        const float mnA = fmaxf(mA, mxA);
        const float mnB = fmaxf(mB, mxB);
        float sumA = 0.f, sumB = 0.f;
        #pragma unroll
        for (int nt = 0; nt < 8; nt++) {
            const int k2 = nt * 8 + 2 * c;
            float p0 = __expf(sAcc[nt][0] - mnA);
            float p1 = __expf(sAcc[nt][1] - mnA);
            float p2 = __expf(sAcc[nt][2] - mnB);
            float p3 = __expf(sAcc[nt][3] - mnB);
            sumA += p0 + p1;
            sumB += p2 + p3;
            float2 pa = { to_tf32(p0), to_tf32(p1) };
            float2 pb = { to_tf32(p2), to_tf32(p3) };
            *(float2*)&Ps[(q0 + r) * AQ + k2] = pa;
            *(float2*)&Ps[(q0 + r + 8) * AQ + k2] = pb;
        }
        sumA += __shfl_xor_sync(0xffffffffu, sumA, 1);
        sumA += __shfl_xor_sync(0xffffffffu, sumA, 2);
        sumB += __shfl_xor_sync(0xffffffffu, sumB, 1);
        sumB += __shfl_xor_sync(0xffffffffu, sumB, 2);

        const float sclA = __expf(mA - mnA);
        const float sclB = __expf(mB - mnB);
        lA = lA * sclA + sumA;  mA = mnA;
        lB = lB * sclB + sumB;  mB = mnB;
        #pragma unroll
        for (int dt = 0; dt < 8; dt++) {
            oAcc[dt][0] *= sclA;  oAcc[dt][1] *= sclA;
            oAcc[dt][2] *= sclB;  oAcc[dt][3] *= sclB;
        }
        __syncwarp();

        // O += P V
        #pragma unroll
        for (int ks = 0; ks < 8; ks++) {
            uint32_t af[4];
            af[0] = __float_as_uint(Ps[(q0 + r) * AQ + ks * 8 + c]);
            af[1] = __float_as_uint(Ps[(q0 + r + 8) * AQ + ks * 8 + c]);
            af[2] = __float_as_uint(Ps[(q0 + r) * AQ + ks * 8 + c + 4]);
            af[3] = __float_as_uint(Ps[(q0 + r + 8) * AQ + ks * 8 + c + 4]);
            #pragma unroll
            for (int dt = 0; dt < 8; dt++) {
                uint32_t bf[2];
                bf[0] = __float_as_uint(Vs[(ks * 8 + c) * AV + dt * 8 + r]);
                bf[1] = __float_as_uint(Vs[(ks * 8 + c + 4) * AV + dt * 8 + r]);
                mma_tf32(oAcc[dt], af, bf);
            }
        }
    }

    // normalize + write ctx[b, s, h*64 + d]
    const float iA = 1.f / lA;
    const float iB = 1.f / lB;
    float* Op = g_ctx + (size_t)(b * SEQ + qb + q0 + r) * DMODEL + h * 64 + 2 * c;
    #pragma unroll
    for (int dt = 0; dt < 8; dt++) {
        float2 vA = { oAcc[dt][0] * iA, oAcc[dt][1] * iA };
        float2 vB = { oAcc[dt][2] * iB, oAcc[dt][3] * iB };
        *(float2*)(Op + dt * 8) = vA;
        *(float2*)(Op + 8 * DMODEL + dt * 8) = vB;
    }
}

// ---------------------------------------------------------------------------
extern "C" void kernel_launch(void* const* d_in, const int* in_sizes, int n_in,
                              void* d_out, int out_size)
{
    const float* x    = (const float*)d_in[0];
    const float* geom = (const float*)d_in[1];
    const int*   mask = (const int*)d_in[2];
    const float* Wq = (const float*)d_in[3];
    const float* bq = (const float*)d_in[4];
    const float* Wk = (const float*)d_in[5];
    const float* bk = (const float*)d_in[6];
    const float* Wv = (const float*)d_in[7];
    const float* bv = (const float*)d_in[8];
    const float* Wo = (const float*)d_in[9];
    const float* bo = (const float*)d_in[10];
    const float* Wg = (const float*)d_in[11];
    const float* bg = (const float*)d_in[12];
    float* out = (float*)d_out;

    cudaFuncSetAttribute(gemm_mma, cudaFuncAttributeMaxDynamicSharedMemorySize, GSMEM_BYTES);
    cudaFuncSetAttribute(attn_mma, cudaFuncAttributeMaxDynamicSharedMemorySize, ASMEM_BYTES);

    // QKV projections
    gemm_mma<<<dim3(24, 32), 256, GSMEM_BYTES>>>(x, Wq, Wk, Wv, bq, bk, bv, nullptr, 0);

    // geometric bias
    geom_bias_kernel<<<(BATCH * SEQ * SEQ) / 256, 256>>>(geom, Wg, bg);

    // attention
    attn_mma<<<dim3(SEQ / 64, NH, BATCH), 128, ASMEM_BYTES>>>(mask);

    // output projection
    gemm_mma<<<dim3(8, 32), 256, GSMEM_BYTES>>>(nullptr, Wo, nullptr, nullptr, bo, nullptr, nullptr, out, 1);
}

// round 5
// speedup vs baseline: 2.3107x; 1.1698x over previous
#include <cuda_runtime.h>
#include <cuda_fp16.h>
#include <math.h>
#include <cstdint>

#define BATCH  4
#define SEQ    1024
#define DMODEL 1024
#define NH     16
#define DK     64

// ---------------- scratch (device globals: allocation-free) ----------------
__device__ float g_Q[BATCH * NH * SEQ * DK];
__device__ float g_K[BATCH * NH * SEQ * DK];
__device__ float g_V[BATCH * NH * SEQ * DK];
__device__ __half g_biash[(size_t)BATCH * NH * SEQ * SEQ];   // 134 MB, mask folded in
__device__ float g_ctx[BATCH * SEQ * DMODEL];

// ---------------- mma.sync tf32 helpers ----------------
__device__ __forceinline__ float to_tf32(float x) {
    uint32_t u;
    asm("cvt.rna.tf32.f32 %0, %1;" : "=r"(u) : "f"(x));
    return __uint_as_float(u);
}
__device__ __forceinline__ void mma_tf32(float c[4], const uint32_t a[4], const uint32_t b[2]) {
    asm volatile("mma.sync.aligned.m16n8k8.row.col.f32.tf32.tf32.f32 "
                 "{%0,%1,%2,%3}, {%4,%5,%6,%7}, {%8,%9}, {%0,%1,%2,%3};"
                 : "+f"(c[0]), "+f"(c[1]), "+f"(c[2]), "+f"(c[3])
                 : "r"(a[0]), "r"(a[1]), "r"(a[2]), "r"(a[3]), "r"(b[0]), "r"(b[1]));
}

// ---------------------------------------------------------------------------
// Tensor GEMM via mma.sync tf32 (unchanged; 105us QKV + 35us outproj)
// ---------------------------------------------------------------------------
#define AP 36
#define BP 136
#define GBUF (128 * AP + 32 * BP)
#define GSMEM_BYTES (2 * GBUF * 4)

__global__ __launch_bounds__(256)
void gemm_mma(const float* __restrict__ A,
              const float* __restrict__ W0, const float* __restrict__ W1,
              const float* __restrict__ W2,
              const float* __restrict__ bias0, const float* __restrict__ bias1,
              const float* __restrict__ bias2,
              float* __restrict__ Cout, int mode)
{
    extern __shared__ float smg[];
    const int tid = threadIdx.x, lane = tid & 31;
    const int wid = tid >> 5;
    const int wm = wid & 3, wn = wid >> 2;
    const int r = lane >> 2, c = lane & 3;

    int mat, bn;
    const float* W;
    const float* bias;
    if (mode == 0) {
        mat = blockIdx.x >> 3;
        bn = (blockIdx.x & 7) * 128;
        W = (mat == 0) ? W0 : (mat == 1) ? W1 : W2;
        bias = (mat == 0) ? bias0 : (mat == 1) ? bias1 : bias2;
    } else {
        mat = 3;
        bn = blockIdx.x * 128;
        W = W0;
        bias = bias0;
    }
    const int bm = blockIdx.y * 128;
    const float* Asrc = (mode == 0) ? A : g_ctx;

    const int arow = tid >> 1;
    const int acb  = (tid & 1) * 16;
    const int brow = tid >> 3;
    const int bcb  = (tid & 7) * 16;
    const float* Apg = Asrc + (size_t)(bm + arow) * 1024 + acb;
    const float* Bpg = W + (size_t)brow * 1024 + bn + bcb;

    float acc[2][8][4];
    #pragma unroll
    for (int im = 0; im < 2; im++)
        #pragma unroll
        for (int in_ = 0; in_ < 8; in_++)
            #pragma unroll
            for (int j = 0; j < 4; j++) acc[im][in_][j] = 0.f;

    float4 ar[4], br[4];
    #pragma unroll
    for (int j = 0; j < 4; j++) {
        ar[j] = *(const float4*)(Apg + j * 4);
        br[j] = *(const float4*)(Bpg + (size_t)0 + j * 4);
    }
    {
        float* Ab = smg;
        float* Bb = smg + 128 * AP;
        #pragma unroll
        for (int j = 0; j < 4; j++) {
            float4 t = { to_tf32(ar[j].x), to_tf32(ar[j].y), to_tf32(ar[j].z), to_tf32(ar[j].w) };
            *(float4*)&Ab[arow * AP + acb + j * 4] = t;
            float4 u = { to_tf32(br[j].x), to_tf32(br[j].y), to_tf32(br[j].z), to_tf32(br[j].w) };
            *(float4*)&Bb[brow * BP + bcb + j * 4] = u;
        }
    }
    __syncthreads();

    for (int s = 0; s < 32; s++) {
        if (s + 1 < 32) {
            const int k0 = (s + 1) * 32;
            #pragma unroll
            for (int j = 0; j < 4; j++) {
                ar[j] = *(const float4*)(Apg + k0 + j * 4);
                br[j] = *(const float4*)(Bpg + (size_t)k0 * 1024 + j * 4);
            }
        }
        const float* Ab = smg + (s & 1) * GBUF;
        const float* Bb = Ab + 128 * AP;
        #pragma unroll
        for (int ks = 0; ks < 4; ks++) {
            uint32_t af[2][4];
            #pragma unroll
            for (int im = 0; im < 2; im++) {
                const int m0 = wm * 32 + im * 16;
                af[im][0] = __float_as_uint(Ab[(m0 + r) * AP + ks * 8 + c]);
                af[im][1] = __float_as_uint(Ab[(m0 + r + 8) * AP + ks * 8 + c]);
                af[im][2] = __float_as_uint(Ab[(m0 + r) * AP + ks * 8 + c + 4]);
                af[im][3] = __float_as_uint(Ab[(m0 + r + 8) * AP + ks * 8 + c + 4]);
            }
            #pragma unroll
            for (int in_ = 0; in_ < 8; in_++) {
                const int n0 = wn * 64 + in_ * 8;
                uint32_t bf[2];
                bf[0] = __float_as_uint(Bb[(ks * 8 + c) * BP + n0 + r]);
                bf[1] = __float_as_uint(Bb[(ks * 8 + c + 4) * BP + n0 + r]);
                mma_tf32(acc[0][in_], af[0], bf);
                mma_tf32(acc[1][in_], af[1], bf);
            }
        }
        if (s + 1 < 32) {
            float* Ab2 = smg + ((s + 1) & 1) * GBUF;
            float* Bb2 = Ab2 + 128 * AP;
            #pragma unroll
            for (int j = 0; j < 4; j++) {
                float4 t = { to_tf32(ar[j].x), to_tf32(ar[j].y), to_tf32(ar[j].z), to_tf32(ar[j].w) };
                *(float4*)&Ab2[arow * AP + acb + j * 4] = t;
                float4 u = { to_tf32(br[j].x), to_tf32(br[j].y), to_tf32(br[j].z), to_tf32(br[j].w) };
                *(float4*)&Bb2[brow * BP + bcb + j * 4] = u;
            }
        }
        __syncthreads();
    }

    #pragma unroll
    for (int im = 0; im < 2; im++) {
        #pragma unroll
        for (int in_ = 0; in_ < 8; in_++) {
            const int m = bm + wm * 32 + im * 16 + r;
            const int n = bn + wn * 64 + in_ * 8 + 2 * c;
            float2 bz = *(const float2*)&bias[n];
            float2 v0 = { acc[im][in_][0] + bz.x, acc[im][in_][1] + bz.y };
            float2 v1 = { acc[im][in_][2] + bz.x, acc[im][in_][3] + bz.y };
            if (mode == 0) {
                const int bb = m >> 10, ss = m & 1023;
                const int hh = n >> 6, dd = n & 63;
                float* dst = ((mat == 0) ? g_Q : (mat == 1) ? g_K : g_V)
                           + ((size_t)((bb * NH + hh) * SEQ + ss)) * DK + dd;
                *(float2*)dst = v0;
                *(float2*)(dst + 8 * DK) = v1;
            } else {
                float* dst = Cout + (size_t)m * 1024 + n;
                *(float2*)dst = v0;
                *(float2*)(dst + 8 * 1024) = v1;
            }
        }
    }
}

// ---------------------------------------------------------------------------
// Geometry bias (fp16, mask folded): g_biash[b,h,q,k] =
//   mask[b,k] ? (geom[b,q,k,:]@Wg + bg) : -30000
// ---------------------------------------------------------------------------
__global__ __launch_bounds__(256)
void geom_bias_kernel(const float* __restrict__ geom, const float* __restrict__ Wg,
                      const float* __restrict__ bg, const int* __restrict__ mask)
{
    __shared__ float wgs[7][16];
    __shared__ float bgs[16];
    int tid = threadIdx.x;
    if (tid < 112) wgs[tid / 16][tid % 16] = Wg[tid];
    if (tid < 16)  bgs[tid] = bg[tid];
    __syncthreads();

    size_t idx = (size_t)blockIdx.x * 256 + tid;
    const float* gp = geom + idx * 7;
    float g[7];
    #pragma unroll
    for (int i = 0; i < 7; i++) g[i] = gp[i];

    int k = (int)(idx & 1023);
    int bq = (int)(idx >> 10);
    int q = bq & 1023;
    int b = bq >> 10;
    const bool live = mask[b * SEQ + k] != 0;
    size_t base = ((size_t)(b * NH) * SEQ + q) * SEQ + k;

    #pragma unroll
    for (int h = 0; h < NH; h++) {
        float v = bgs[h];
        #pragma unroll
        for (int i = 0; i < 7; i++) v += g[i] * wgs[i][h];
        g_biash[base + (size_t)h * SEQ * SEQ] = __float2half(live ? v : -30000.f);
    }
}

// ---------------------------------------------------------------------------
// Flash attention v2: 256 threads / 8 warps, q-tile 128 (16 q-rows per warp).
// Fpair layout for Q/K/P; V interleaved with d-group XOR swizzle (key is a
// function of the d-column group on BOTH write and read — R4 bug was using
// the k-group at read). Bias fp16 from gmem, mask pre-folded.
// ---------------------------------------------------------------------------
#define QP 72
#define KP 72
#define PP 72
#define VP 136
#define ASMEM_FLOATS (128 * QP + 64 * KP + 128 * PP + 32 * VP)
#define ASMEM_BYTES (ASMEM_FLOATS * 4)

__global__ __launch_bounds__(256, 2)
void attn_mma()
{
    extern __shared__ float smf[];
    float* Qs = smf;                   // [128][QP]  Fpair
    float* Ks = Qs + 128 * QP;         // [64][KP]   Fpair
    float* Ps = Ks + 64 * KP;          // [128][PP]  Fpair
    float* Vf = Ps + 128 * PP;         // [32][VP]   interleaved + XOR swizzle

    const int qb = blockIdx.x * 128;
    const int h  = blockIdx.y;
    const int b  = blockIdx.z;
    const float* Qp = g_Q + (size_t)((b * NH + h) * SEQ) * DK;
    const float* Kp = g_K + (size_t)((b * NH + h) * SEQ) * DK;
    const float* Vp = g_V + (size_t)((b * NH + h) * SEQ) * DK;
    const __half* Bh = g_biash + (size_t)(b * NH + h) * SEQ * SEQ;

    const int tid = threadIdx.x;
    const int lane = tid & 31, wid = tid >> 5;
    const int r = lane >> 2, c = lane & 3;
    const int q0 = wid * 16;

    // ---- load Q tile into Fpair layout (float2 stores pair cols c / c+4) ----
    {
        const int row = tid >> 1;
        const int db  = (tid & 1) * 32;
        const float* src = Qp + (size_t)(qb + row) * DK + db;
        float* drow = Qs + row * QP;
        #pragma unroll
        for (int gg = 0; gg < 4; gg++) {
            float4 v0 = *(const float4*)(src + gg * 8);
            float4 v1 = *(const float4*)(src + gg * 8 + 4);
            float lo[4] = { v0.x, v0.y, v0.z, v0.w };
            float hi[4] = { v1.x, v1.y, v1.z, v1.w };
            #pragma unroll
            for (int j = 0; j < 4; j++) {
                float2 t = { to_tf32(lo[j]), to_tf32(hi[j]) };
                *(float2*)&drow[db + gg * 8 + 2 * j] = t;
            }
        }
    }

    float oAcc[8][4];
    #pragma unroll
    for (int dt = 0; dt < 8; dt++)
        #pragma unroll
        for (int j = 0; j < 4; j++) oAcc[dt][j] = 0.f;
    float mA = -1e30f, mB = -1e30f, lA = 0.f, lB = 0.f;

    for (int kt = 0; kt < 16; kt++) {
        const int kb = kt * 64;
        __syncthreads();
        // ---- load K (Fpair) and V (interleaved+swizzle) ----
        {
            const int row = tid >> 2;             // 0..63
            const int db  = (tid & 3) * 16;
            const float* ksrc = Kp + (size_t)(kb + row) * DK + db;
            const float* vsrc = Vp + (size_t)(kb + row) * DK + db;
            float* krow = Ks + row * KP;
            const int g_  = row >> 3;
            const int rowphys = g_ * 4 + (row & 3);
            const int slot = (row >> 2) & 1;
            float* vrow = Vf + rowphys * VP;
            #pragma unroll
            for (int gg = 0; gg < 2; gg++) {
                float4 k0 = *(const float4*)(ksrc + gg * 8);
                float4 k1 = *(const float4*)(ksrc + gg * 8 + 4);
                float4 u0 = *(const float4*)(vsrc + gg * 8);
                float4 u1 = *(const float4*)(vsrc + gg * 8 + 4);
                float klo[4] = { k0.x, k0.y, k0.z, k0.w };
                float khi[4] = { k1.x, k1.y, k1.z, k1.w };
                float va[8] = { u0.x, u0.y, u0.z, u0.w, u1.x, u1.y, u1.z, u1.w };
                #pragma unroll
                for (int j = 0; j < 4; j++) {
                    float2 t = { to_tf32(klo[j]), to_tf32(khi[j]) };
                    *(float2*)&krow[db + gg * 8 + 2 * j] = t;
                }
                const int dgrp = (db + gg * 8) >> 3;      // d-column group
                const int key = (dgrp & 3) << 3;
                #pragma unroll
                for (int e = 0; e < 8; e++) {
                    const int d = db + gg * 8 + e;
                    const int phys = (2 * d + slot) ^ key;
                    vrow[phys] = to_tf32(va[e]);
                }
            }
        }
        __syncthreads();

        // ---- S = Q K^T ----
        float sAcc[8][4];
        #pragma unroll
        for (int nt = 0; nt < 8; nt++)
            #pragma unroll
            for (int j = 0; j < 4; j++) sAcc[nt][j] = 0.f;
        #pragma unroll
        for (int ks = 0; ks < 8; ks++) {
            float2 a0 = *(const float2*)&Qs[(q0 + r) * QP + ks * 8 + 2 * c];
            float2 a1 = *(const float2*)&Qs[(q0 + r + 8) * QP + ks * 8 + 2 * c];
            uint32_t af[4] = { __float_as_uint(a0.x), __float_as_uint(a1.x),
                               __float_as_uint(a0.y), __float_as_uint(a1.y) };
            #pragma unroll
            for (int nt = 0; nt < 8; nt++) {
                float2 bv = *(const float2*)&Ks[(nt * 8 + r) * KP + ks * 8 + 2 * c];
                uint32_t bf[2] = { __float_as_uint(bv.x), __float_as_uint(bv.y) };
                mma_tf32(sAcc[nt], af, bf);
            }
        }

        // ---- scale + bias (mask pre-folded), row max ----
        float mxA = -1e30f, mxB = -1e30f;
        const __half2* BpA = (const __half2*)(Bh + (size_t)(qb + q0 + r) * SEQ + kb);
        const __half2* BpB = (const __half2*)(Bh + (size_t)(qb + q0 + r + 8) * SEQ + kb);
        #pragma unroll
        for (int nt = 0; nt < 8; nt++) {
            float2 bzA = __half22float2(BpA[nt * 4 + c]);
            float2 bzB = __half22float2(BpB[nt * 4 + c]);
            sAcc[nt][0] = fmaf(sAcc[nt][0], 0.125f, bzA.x);
            sAcc[nt][1] = fmaf(sAcc[nt][1], 0.125f, bzA.y);
            sAcc[nt][2] = fmaf(sAcc[nt][2], 0.125f, bzB.x);
            sAcc[nt][3] = fmaf(sAcc[nt][3], 0.125f, bzB.y);
            mxA = fmaxf(mxA, fmaxf(sAcc[nt][0], sAcc[nt][1]));
            mxB = fmaxf(mxB, fmaxf(sAcc[nt][2], sAcc[nt][3]));
        }
        mxA = fmaxf(mxA, __shfl_xor_sync(0xffffffffu, mxA, 1));
        mxA = fmaxf(mxA, __shfl_xor_sync(0xffffffffu, mxA, 2));
        mxB = fmaxf(mxB, __shfl_xor_sync(0xffffffffu, mxB, 1));
        mxB = fmaxf(mxB, __shfl_xor_sync(0xffffffffu, mxB, 2));

        const float mnA = fmaxf(mA, mxA);
        const float mnB = fmaxf(mB, mxB);
        float sumA = 0.f, sumB = 0.f;
        const int col0 = (c < 2) ? 4 * c : 4 * c - 7;
        const int col1 = (c < 2) ? 4 * c + 2 : 4 * c - 5;
        float* PrA = Ps + (q0 + r) * PP;
        float* PrB = Ps + (q0 + r + 8) * PP;
        #pragma unroll
        for (int nt = 0; nt < 8; nt++) {
            float p0 = __expf(sAcc[nt][0] - mnA);
            float p1 = __expf(sAcc[nt][1] - mnA);
            float p2 = __expf(sAcc[nt][2] - mnB);
            float p3 = __expf(sAcc[nt][3] - mnB);
            sumA += p0 + p1;
            sumB += p2 + p3;
            PrA[nt * 8 + col0] = to_tf32(p0);
            PrA[nt * 8 + col1] = to_tf32(p1);
            PrB[nt * 8 + col0] = to_tf32(p2);
            PrB[nt * 8 + col1] = to_tf32(p3);
        }
        sumA += __shfl_xor_sync(0xffffffffu, sumA, 1);
        sumA += __shfl_xor_sync(0xffffffffu, sumA, 2);
        sumB += __shfl_xor_sync(0xffffffffu, sumB, 1);
        sumB += __shfl_xor_sync(0xffffffffu, sumB, 2);

        const float sclA = __expf(mA - mnA);
        const float sclB = __expf(mB - mnB);
        lA = lA * sclA + sumA;  mA = mnA;
        lB = lB * sclB + sumB;  mB = mnB;
        #pragma unroll
        for (int dt = 0; dt < 8; dt++) {
            oAcc[dt][0] *= sclA;  oAcc[dt][1] *= sclA;
            oAcc[dt][2] *= sclB;  oAcc[dt][3] *= sclB;
        }
        __syncwarp();

        // ---- O += P V  (read key matches write: function of d-group dt) ----
        #pragma unroll
        for (int ks = 0; ks < 8; ks++) {
            float2 p0 = *(const float2*)&Ps[(q0 + r) * PP + ks * 8 + 2 * c];
            float2 p1 = *(const float2*)&Ps[(q0 + r + 8) * PP + ks * 8 + 2 * c];
            uint32_t af[4] = { __float_as_uint(p0.x), __float_as_uint(p1.x),
                               __float_as_uint(p0.y), __float_as_uint(p1.y) };
            const float* vrow = Vf + (ks * 4 + c) * VP;
            #pragma unroll
            for (int dt = 0; dt < 8; dt++) {
                const int key = (dt & 3) << 3;            // FIX: d-group key
                const int phys = (2 * (dt * 8 + r)) ^ key;
                float2 vv = *(const float2*)&vrow[phys];
                uint32_t bf[2] = { __float_as_uint(vv.x), __float_as_uint(vv.y) };
                mma_tf32(oAcc[dt], af, bf);
            }
        }
    }

    // ---- normalize + write ctx[b, s, h*64 + d] ----
    const float iA = 1.f / lA;
    const float iB = 1.f / lB;
    float* Op = g_ctx + (size_t)(b * SEQ + qb + q0 + r) * DMODEL + h * 64 + 2 * c;
    #pragma unroll
    for (int dt = 0; dt < 8; dt++) {
        float2 vA = { oAcc[dt][0] * iA, oAcc[dt][1] * iA };
        float2 vB = { oAcc[dt][2] * iB, oAcc[dt][3] * iB };
        *(float2*)(Op + dt * 8) = vA;
        *(float2*)(Op + 8 * DMODEL + dt * 8) = vB;
    }
}

// ---------------------------------------------------------------------------
extern "C" void kernel_launch(void* const* d_in, const int* in_sizes, int n_in,
                              void* d_out, int out_size)
{
    const float* x    = (const float*)d_in[0];
    const float* geom = (const float*)d_in[1];
    const int*   mask = (const int*)d_in[2];
    const float* Wq = (const float*)d_in[3];
    const float* bq = (const float*)d_in[4];
    const float* Wk = (const float*)d_in[5];
    const float* bk = (const float*)d_in[6];
    const float* Wv = (const float*)d_in[7];
    const float* bv = (const float*)d_in[8];
    const float* Wo = (const float*)d_in[9];
    const float* bo = (const float*)d_in[10];
    const float* Wg = (const float*)d_in[11];
    const float* bg = (const float*)d_in[12];
    float* out = (float*)d_out;

    cudaFuncSetAttribute(gemm_mma, cudaFuncAttributeMaxDynamicSharedMemorySize, GSMEM_BYTES);
    cudaFuncSetAttribute(attn_mma, cudaFuncAttributeMaxDynamicSharedMemorySize, ASMEM_BYTES);

    // QKV projections
    gemm_mma<<<dim3(24, 32), 256, GSMEM_BYTES>>>(x, Wq, Wk, Wv, bq, bk, bv, nullptr, 0);

    // geometric bias (fp16, mask folded)
    geom_bias_kernel<<<(BATCH * SEQ * SEQ) / 256, 256>>>(geom, Wg, bg, mask);

    // attention
    attn_mma<<<dim3(SEQ / 128, NH, BATCH), 256, ASMEM_BYTES>>>();

    // output projection
    gemm_mma<<<dim3(8, 32), 256, GSMEM_BYTES>>>(nullptr, Wo, nullptr, nullptr, bo, nullptr, nullptr, out, 1);
}